// round 1
// baseline (speedup 1.0000x reference)
#include <cuda_runtime.h>

// SinkhornDistance: B=64, N=M=1024, eps=0.1, 50 iterations.
// Scaling-domain formulation: K = exp(-C/eps); a = (mu+1e-8)/(K b); b = (nu+1e-8)/(K^T a)
// pi = K * a_i * b_j ; cost_b = sum_ij pi*C with C = -eps*log(K).
//
// L2 blocking: batches processed in groups of <=22 (88MB K slab resident in L2),
// all 50 iterations per group before moving on.

#define BATCH 64
#define NN 1024
#define EPSI 0.1f
#define INV_EPS 10.0f
#define LOGEPS 1e-8f
#define MAX_ITER 50
#define EXP10 22026.4657948f  // exp(1/eps), b for v0 = 1

// Scratch (static device globals; no runtime allocation)
__device__ float g_K[(size_t)BATCH * NN * NN];   // 256 MB
__device__ float g_a[BATCH * NN];
__device__ float g_T[2][BATCH * NN];             // double-buffered column sums

// ---------------------------------------------------------------------------
// K = exp(-C/eps). 64M elems = 16M float4 = 65536 blocks x 256 threads exactly.
__global__ void k_precompute(const float* __restrict__ C) {
    size_t i = (size_t)blockIdx.x * blockDim.x + threadIdx.x;
    float4 c = ((const float4*)C)[i];
    float4 k;
    k.x = __expf(-c.x * INV_EPS);
    k.y = __expf(-c.y * INV_EPS);
    k.z = __expf(-c.z * INV_EPS);
    k.w = __expf(-c.w * INV_EPS);
    ((float4*)g_K)[i] = k;
}

// Zero the cost output (d_out poisoned to 0xAA by harness).
__global__ void k_init_cost(float* __restrict__ cost) {
    if (threadIdx.x < BATCH) cost[threadIdx.x] = 0.0f;
}

// ---------------------------------------------------------------------------
// Row pass: for each row i of batch: S_i = sum_j K[b,i,j]*bvec[j]; a = (mu+1e-8)/S.
// bvec computed in-smem from T[(iter-1)&1] (or EXP10 at iter 0).
// Also zeroes T[iter&1] for this batch (one block per batch) ahead of col_pass.
// 256 threads = 8 warps = 8 rows per block; 128 blocks per batch.
__global__ void __launch_bounds__(256) row_pass(
    const float* __restrict__ mu, const float* __restrict__ nu,
    int group_start, int iter)
{
    __shared__ float bsh[NN];
    const int blocksPerBatch = NN / 8;  // 128
    int batch = group_start + blockIdx.x / blocksPerBatch;
    int rowBase = (blockIdx.x % blocksPerBatch) * 8;
    int tid = threadIdx.x;

    const float* __restrict__ Tread = &g_T[(iter + 1) & 1][batch * NN];
    if (iter == 0) {
        for (int j = tid; j < NN; j += 256) bsh[j] = EXP10;
    } else {
        for (int j = tid; j < NN; j += 256)
            bsh[j] = (nu[batch * NN + j] + LOGEPS) / Tread[j];
    }
    // One block per batch zeroes the accumulation buffer for this iteration's col pass.
    if ((blockIdx.x % blocksPerBatch) == 0) {
        float* Tz = &g_T[iter & 1][batch * NN];
        for (int j = tid; j < NN; j += 256) Tz[j] = 0.0f;
    }
    __syncthreads();

    int warp = tid >> 5, lane = tid & 31;
    int row = rowBase + warp;
    const float4* __restrict__ Krow =
        (const float4*)(g_K + ((size_t)batch * NN + row) * NN);
    const float4* __restrict__ bsh4 = (const float4*)bsh;

    float s = 0.0f;
#pragma unroll
    for (int k = 0; k < 8; k++) {
        int idx = k * 32 + lane;
        float4 kv = Krow[idx];
        float4 bv = bsh4[idx];
        s += kv.x * bv.x + kv.y * bv.y + kv.z * bv.z + kv.w * bv.w;
    }
#pragma unroll
    for (int o = 16; o; o >>= 1) s += __shfl_xor_sync(0xffffffffu, s, o);
    if (lane == 0)
        g_a[batch * NN + row] = (mu[batch * NN + row] + LOGEPS) / s;
}

// ---------------------------------------------------------------------------
// Column pass: T_j += sum_{i in chunk} K[b,i,j]*a_i (atomic accumulate).
// Block = 256 threads, each thread owns 4 consecutive columns (float4).
// RCHUNK = 64 rows per block -> 16 blocks per batch.
#define RCHUNK 64
__global__ void __launch_bounds__(256) col_pass(int group_start, int iter) {
    __shared__ float ash[RCHUNK];
    const int chunksPerBatch = NN / RCHUNK;  // 16
    int batch = group_start + blockIdx.x / chunksPerBatch;
    int r0 = (blockIdx.x % chunksPerBatch) * RCHUNK;
    int tid = threadIdx.x;

    if (tid < RCHUNK) ash[tid] = g_a[batch * NN + r0 + tid];
    __syncthreads();

    const float4* __restrict__ Kb = (const float4*)(g_K + (size_t)batch * NN * NN);
    float4 acc = make_float4(0.f, 0.f, 0.f, 0.f);
#pragma unroll 4
    for (int i = 0; i < RCHUNK; i++) {
        float a = ash[i];
        float4 kv = Kb[(size_t)(r0 + i) * (NN / 4) + tid];
        acc.x += kv.x * a;
        acc.y += kv.y * a;
        acc.z += kv.z * a;
        acc.w += kv.w * a;
    }
    float* T = &g_T[iter & 1][batch * NN + tid * 4];
    atomicAdd(T + 0, acc.x);
    atomicAdd(T + 1, acc.y);
    atomicAdd(T + 2, acc.z);
    atomicAdd(T + 3, acc.w);
}

// ---------------------------------------------------------------------------
// Epilogue: pi = K*a_i*b_j; cost_b += sum pi*C with C = -eps*log(K).
__global__ void __launch_bounds__(256) epilogue(
    const float* __restrict__ nu, float* __restrict__ out_cost,
    float* __restrict__ out_pi)
{
    __shared__ float bsh[NN];
    const int blocksPerBatch = NN / 8;
    int batch = blockIdx.x / blocksPerBatch;
    int rowBase = (blockIdx.x % blocksPerBatch) * 8;
    int tid = threadIdx.x;

    const float* __restrict__ T = &g_T[(MAX_ITER - 1) & 1][batch * NN];
    for (int j = tid; j < NN; j += 256)
        bsh[j] = (nu[batch * NN + j] + LOGEPS) / T[j];
    __syncthreads();

    int warp = tid >> 5, lane = tid & 31;
    int row = rowBase + warp;
    float a = g_a[batch * NN + row];
    const float4* __restrict__ Krow =
        (const float4*)(g_K + ((size_t)batch * NN + row) * NN);
    float4* __restrict__ Prow =
        (float4*)(out_pi + ((size_t)batch * NN + row) * NN);
    const float4* __restrict__ bsh4 = (const float4*)bsh;

    float cacc = 0.0f;
#pragma unroll
    for (int k = 0; k < 8; k++) {
        int idx = k * 32 + lane;
        float4 kv = Krow[idx];
        float4 bv = bsh4[idx];
        float4 p;
        p.x = kv.x * a * bv.x;
        p.y = kv.y * a * bv.y;
        p.z = kv.z * a * bv.z;
        p.w = kv.w * a * bv.w;
        // C = -eps * log(K)
        cacc += p.x * (-EPSI * __logf(kv.x));
        cacc += p.y * (-EPSI * __logf(kv.y));
        cacc += p.z * (-EPSI * __logf(kv.z));
        cacc += p.w * (-EPSI * __logf(kv.w));
        Prow[idx] = p;
    }
#pragma unroll
    for (int o = 16; o; o >>= 1) cacc += __shfl_xor_sync(0xffffffffu, cacc, o);
    if (lane == 0) atomicAdd(&out_cost[batch], cacc);
}

// ---------------------------------------------------------------------------
extern "C" void kernel_launch(void* const* d_in, const int* in_sizes, int n_in,
                              void* d_out, int out_size) {
    const float* mu = (const float*)d_in[0];
    const float* nu = (const float*)d_in[1];
    const float* C  = (const float*)d_in[2];
    float* cost = (float*)d_out;                 // outputs: (cost[64], pi[64M])
    float* pi   = (float*)d_out + BATCH;

    // Prologue
    k_precompute<<<65536, 256>>>(C);             // 16M float4 exactly
    k_init_cost<<<1, 64>>>(cost);

    // L2-blocked iteration: groups of batches whose K slab fits in L2 (<=88MB).
    const int GS[3] = {22, 21, 21};
    int start = 0;
    for (int g = 0; g < 3; g++) {
        int nb = GS[g];
        for (int it = 0; it < MAX_ITER; it++) {
            row_pass<<<nb * (NN / 8), 256>>>(mu, nu, start, it);
            col_pass<<<nb * (NN / RCHUNK), 256>>>(start, it);
        }
        start += nb;
    }

    // Epilogue over all batches
    epilogue<<<BATCH * (NN / 8), 256>>>(nu, cost, pi);
}

// round 2
// speedup vs baseline: 1.2425x; 1.2425x over previous
#include <cuda_runtime.h>

// SinkhornDistance: B=64, N=M=1024, eps=0.1, 50 iterations.
// Scaling domain: K = exp(-C/eps); a = (mu+1e-8)/(K b); b = (nu+1e-8)/(K^T a)
// pi = K * a_i * b_j ; cost_b = sum_ij pi*C with C = -eps*log(K).
//
// R2: fused row+col pass (single K read per iteration, K tile held in regs),
// 16-batch groups (64MB L2 slab), 3-buffer zero-ahead rotation for the
// atomic column-sum target, per-group precompute/epilogue for warm L2.

#define BATCH 64
#define NN 1024
#define EPSI 0.1f
#define INV_EPS 10.0f
#define LOGEPS 1e-8f
#define MAX_ITER 50
#define EXP10 22026.4657948f  // exp(1/eps) -> b for v0 = 1

#define GSZ 16   // batches per group (4 groups)
#define RPB 16   // rows per block (two halves of 8)
#define BPB (NN / RPB)  // 64 blocks per batch

// Scratch (static device globals; no runtime allocation)
__device__ float g_K[(size_t)BATCH * NN * NN];   // 256 MB
__device__ float g_a[BATCH * NN];
__device__ float g_T[3][BATCH * NN];             // rotation buffers (col sums)

// ---------------------------------------------------------------------------
// K = exp(-C/eps) for one group's slab. grid covers GSZ*1M floats as float4.
__global__ void __launch_bounds__(256) k_precompute(const float* __restrict__ C,
                                                    int group_start) {
    size_t base = (size_t)group_start * NN * NN / 4;
    size_t i = base + (size_t)blockIdx.x * blockDim.x + threadIdx.x;
    float4 c = ((const float4*)C)[i];
    float4 k;
    k.x = __expf(-c.x * INV_EPS);
    k.y = __expf(-c.y * INV_EPS);
    k.z = __expf(-c.z * INV_EPS);
    k.w = __expf(-c.w * INV_EPS);
    ((float4*)g_K)[i] = k;
}

// Zero cost[64] and T[0] for all batches. grid = 64 blocks x 256 threads.
__global__ void k_init(float* __restrict__ cost) {
    int idx = blockIdx.x * 256 + threadIdx.x;  // 16384 float4 = 64K floats
    ((float4*)g_T[0])[idx] = make_float4(0.f, 0.f, 0.f, 0.f);
    if (blockIdx.x == 0 && threadIdx.x < BATCH) cost[threadIdx.x] = 0.0f;
}

// ---------------------------------------------------------------------------
// Fused iteration: block owns 16 rows of one batch; thread owns 4 columns.
// Phase 1: row dots s_i = sum_j K_ij b_j  ->  a_i = (mu_i+1e-8)/s_i
// Phase 2: column partials acc_j = sum_{i in block} K_ij a_i -> atomicAdd(T)
// K tile held in registers between phases (read exactly once).
// Buffers: read T[(it+2)%3], write T[it%3], zero-ahead T[(it+1)%3].
__global__ void __launch_bounds__(256) fused_iter(
    const float* __restrict__ mu, const float* __restrict__ nu,
    int group_start, int iter)
{
    int batch = group_start + blockIdx.x / BPB;
    int r0 = (blockIdx.x % BPB) * RPB;
    int tid = threadIdx.x;
    int lane = tid & 31, warp = tid >> 5;

    // b at this thread's 4 columns
    float4 bv;
    if (iter == 0) {
        bv = make_float4(EXP10, EXP10, EXP10, EXP10);
    } else {
        float4 t = ((const float4*)&g_T[(iter + 2) % 3][(size_t)batch * NN])[tid];
        float4 n = ((const float4*)(nu + (size_t)batch * NN))[tid];
        bv.x = (n.x + LOGEPS) / t.x;
        bv.y = (n.y + LOGEPS) / t.y;
        bv.z = (n.z + LOGEPS) / t.z;
        bv.w = (n.w + LOGEPS) / t.w;
    }

    // Zero-ahead: buffer (iter+1)%3 is untouched by every other block this
    // launch (last read happened in the previous launch), so this is race-free.
    if ((blockIdx.x % BPB) == 0) {
        ((float4*)&g_T[(iter + 1) % 3][(size_t)batch * NN])[tid] =
            make_float4(0.f, 0.f, 0.f, 0.f);
    }

    const float4* __restrict__ Kb =
        (const float4*)(g_K + (size_t)batch * NN * NN);

    __shared__ float wsum[8][8];
    __shared__ float ash[8];
    float4 acc = make_float4(0.f, 0.f, 0.f, 0.f);

#pragma unroll
    for (int h = 0; h < 2; h++) {
        int rb = r0 + h * 8;
        float4 kv[8];
        float part[8];
#pragma unroll
        for (int r = 0; r < 8; r++) {
            kv[r] = Kb[(size_t)(rb + r) * (NN / 4) + tid];
            part[r] = kv[r].x * bv.x + kv[r].y * bv.y +
                      kv[r].z * bv.z + kv[r].w * bv.w;
        }
#pragma unroll
        for (int r = 0; r < 8; r++) {
            float s = part[r];
#pragma unroll
            for (int o = 16; o; o >>= 1) s += __shfl_xor_sync(0xffffffffu, s, o);
            if (lane == 0) wsum[r][warp] = s;
        }
        __syncthreads();
        if (tid < 8) {
            float s = 0.f;
#pragma unroll
            for (int w = 0; w < 8; w++) s += wsum[tid][w];
            float a = (mu[(size_t)batch * NN + rb + tid] + LOGEPS) / s;
            ash[tid] = a;
            if (iter == MAX_ITER - 1) g_a[batch * NN + rb + tid] = a;
        }
        __syncthreads();
#pragma unroll
        for (int r = 0; r < 8; r++) {
            float a = ash[r];
            acc.x += kv[r].x * a;
            acc.y += kv[r].y * a;
            acc.z += kv[r].z * a;
            acc.w += kv[r].w * a;
        }
        if (h == 0) __syncthreads();  // ash/wsum reuse barrier
    }

    float* T = &g_T[iter % 3][(size_t)batch * NN] + tid * 4;
    atomicAdd(T + 0, acc.x);
    atomicAdd(T + 1, acc.y);
    atomicAdd(T + 2, acc.z);
    atomicAdd(T + 3, acc.w);
}

// ---------------------------------------------------------------------------
// Epilogue (per group, runs while K slab is L2-warm):
// pi = K*a_i*b_j; cost_b += sum pi*C with C = -eps*log(K).
// Final T buffer index: (MAX_ITER-1)%3.
__global__ void __launch_bounds__(256) epilogue(
    const float* __restrict__ nu, float* __restrict__ out_cost,
    float* __restrict__ out_pi, int group_start)
{
    __shared__ float bsh[NN];
    const int blocksPerBatch = NN / 8;
    int batch = group_start + blockIdx.x / blocksPerBatch;
    int rowBase = (blockIdx.x % blocksPerBatch) * 8;
    int tid = threadIdx.x;

    const float* __restrict__ T = &g_T[(MAX_ITER - 1) % 3][(size_t)batch * NN];
    for (int j = tid; j < NN; j += 256)
        bsh[j] = (nu[(size_t)batch * NN + j] + LOGEPS) / T[j];
    __syncthreads();

    int warp = tid >> 5, lane = tid & 31;
    int row = rowBase + warp;
    float a = g_a[batch * NN + row];
    const float4* __restrict__ Krow =
        (const float4*)(g_K + ((size_t)batch * NN + row) * NN);
    float4* __restrict__ Prow =
        (float4*)(out_pi + ((size_t)batch * NN + row) * NN);
    const float4* __restrict__ bsh4 = (const float4*)bsh;

    float cacc = 0.0f;
#pragma unroll
    for (int k = 0; k < 8; k++) {
        int idx = k * 32 + lane;
        float4 kv = Krow[idx];
        float4 bv = bsh4[idx];
        float4 p;
        p.x = kv.x * a * bv.x;
        p.y = kv.y * a * bv.y;
        p.z = kv.z * a * bv.z;
        p.w = kv.w * a * bv.w;
        cacc += p.x * (-EPSI * __logf(kv.x));
        cacc += p.y * (-EPSI * __logf(kv.y));
        cacc += p.z * (-EPSI * __logf(kv.z));
        cacc += p.w * (-EPSI * __logf(kv.w));
        Prow[idx] = p;
    }
#pragma unroll
    for (int o = 16; o; o >>= 1) cacc += __shfl_xor_sync(0xffffffffu, cacc, o);
    if (lane == 0) atomicAdd(&out_cost[batch], cacc);
}

// ---------------------------------------------------------------------------
extern "C" void kernel_launch(void* const* d_in, const int* in_sizes, int n_in,
                              void* d_out, int out_size) {
    const float* mu = (const float*)d_in[0];
    const float* nu = (const float*)d_in[1];
    const float* C  = (const float*)d_in[2];
    float* cost = (float*)d_out;                 // outputs: (cost[64], pi[64M])
    float* pi   = (float*)d_out + BATCH;

    k_init<<<64, 256>>>(cost);

    const int precompBlocks = GSZ * NN * NN / 4 / 256;  // 16384
    for (int g = 0; g < BATCH / GSZ; g++) {
        int start = g * GSZ;
        k_precompute<<<precompBlocks, 256>>>(C, start);
        for (int it = 0; it < MAX_ITER; it++) {
            fused_iter<<<GSZ * BPB, 256>>>(mu, nu, start, it);
        }
        epilogue<<<GSZ * (NN / 8), 256>>>(nu, cost, pi, start);
    }
}

// round 3
// speedup vs baseline: 1.6394x; 1.3195x over previous
#include <cuda_runtime.h>
#include <cuda_fp16.h>

// SinkhornDistance: B=64, N=M=1024, eps=0.1, 50 iterations.
// Scaling domain: K = exp(-C/eps); a = (mu+1e-8)/(K b); b = (nu+1e-8)/(K^T a)
// pi = exp(-C/eps) * a_i * b_j (fp32, on the fly) ; cost_b = sum pi*C.
//
// R3: K stored fp16 for the 50 iterations -> 32-batch groups are a 64MB L2
// slab covering 2x batches per launch (100 fused launches instead of 200,
// half the total iteration traffic). Epilogue reads C directly and computes
// K in fp32 on the fly (no log, no fp32 K storage).

#define BATCH 64
#define NN 1024
#define INV_EPS 10.0f
#define LOGEPS 1e-8f
#define MAX_ITER 50
#define EXP10 22026.4657948f  // exp(1/eps) -> b for v0 = 1

#define GSZ 32               // batches per group (2 groups)
#define RPB 16               // rows per block
#define BPB (NN / RPB)       // 64 blocks per batch

// Scratch (static device globals; no runtime allocation)
__device__ __half g_K16[(size_t)BATCH * NN * NN];  // 128 MB
__device__ float g_a[BATCH * NN];
__device__ float g_T[3][BATCH * NN];               // rotation buffers

// ---------------------------------------------------------------------------
// K16 = fp16(exp(-C/eps)) for one group's slab. Thread handles 4 elements.
__global__ void __launch_bounds__(256) k_precompute16(const float* __restrict__ C,
                                                      int group_start) {
    size_t base = (size_t)group_start * NN * NN;
    size_t i = base + ((size_t)blockIdx.x * 256 + threadIdx.x) * 4;
    float4 c = *(const float4*)(C + i);
    __half2 h0 = __floats2half2_rn(__expf(-c.x * INV_EPS), __expf(-c.y * INV_EPS));
    __half2 h1 = __floats2half2_rn(__expf(-c.z * INV_EPS), __expf(-c.w * INV_EPS));
    uint2 pk;
    pk.x = *(const unsigned int*)&h0;
    pk.y = *(const unsigned int*)&h1;
    *(uint2*)(g_K16 + i) = pk;
}

// Zero cost[64] and T[0] for all batches. grid = 64 blocks x 256 threads.
__global__ void k_init(float* __restrict__ cost) {
    int idx = blockIdx.x * 256 + threadIdx.x;  // 16384 float4 = 64K floats
    ((float4*)g_T[0])[idx] = make_float4(0.f, 0.f, 0.f, 0.f);
    if (blockIdx.x == 0 && threadIdx.x < BATCH) cost[threadIdx.x] = 0.0f;
}

// ---------------------------------------------------------------------------
// Fused iteration on fp16 K: block owns 16 rows of one batch; thread owns 4
// columns. Tile held in regs (fp16, 16 regs) between row-dot and col-acc
// phases; K read exactly once per iteration.
// Buffers: read T[(it+2)%3], write T[it%3], zero-ahead T[(it+1)%3].
__global__ void __launch_bounds__(256) fused_iter(
    const float* __restrict__ mu, const float* __restrict__ nu,
    int group_start, int iter)
{
    int batch = group_start + blockIdx.x / BPB;
    int r0 = (blockIdx.x % BPB) * RPB;
    int tid = threadIdx.x;
    int lane = tid & 31, warp = tid >> 5;

    // b at this thread's 4 columns
    float4 bv;
    if (iter == 0) {
        bv = make_float4(EXP10, EXP10, EXP10, EXP10);
    } else {
        float4 t = ((const float4*)&g_T[(iter + 2) % 3][(size_t)batch * NN])[tid];
        float4 n = ((const float4*)(nu + (size_t)batch * NN))[tid];
        bv.x = (n.x + LOGEPS) / t.x;
        bv.y = (n.y + LOGEPS) / t.y;
        bv.z = (n.z + LOGEPS) / t.z;
        bv.w = (n.w + LOGEPS) / t.w;
    }

    // Zero-ahead: buffer (iter+1)%3 is untouched by all other blocks this
    // launch (last read was in the previous launch) -> race-free.
    if ((blockIdx.x % BPB) == 0) {
        ((float4*)&g_T[(iter + 1) % 3][(size_t)batch * NN])[tid] =
            make_float4(0.f, 0.f, 0.f, 0.f);
    }

    const uint2* __restrict__ Kb =
        (const uint2*)(g_K16 + (size_t)batch * NN * NN);

    __shared__ float wsum[8][8];
    __shared__ float ash[8];
    float4 acc = make_float4(0.f, 0.f, 0.f, 0.f);

#pragma unroll
    for (int h = 0; h < 2; h++) {
        int rb = r0 + h * 8;
        uint2 kv[8];
        float part[8];
#pragma unroll
        for (int r = 0; r < 8; r++)
            kv[r] = Kb[(size_t)(rb + r) * (NN / 4) + tid];
#pragma unroll
        for (int r = 0; r < 8; r++) {
            float2 f01 = __half22float2(*(__half2*)&kv[r].x);
            float2 f23 = __half22float2(*(__half2*)&kv[r].y);
            part[r] = f01.x * bv.x + f01.y * bv.y + f23.x * bv.z + f23.y * bv.w;
        }
#pragma unroll
        for (int r = 0; r < 8; r++) {
            float s = part[r];
#pragma unroll
            for (int o = 16; o; o >>= 1) s += __shfl_xor_sync(0xffffffffu, s, o);
            if (lane == 0) wsum[r][warp] = s;
        }
        __syncthreads();
        if (tid < 8) {
            float s = 0.f;
#pragma unroll
            for (int w = 0; w < 8; w++) s += wsum[tid][w];
            float a = (mu[(size_t)batch * NN + rb + tid] + LOGEPS) / s;
            ash[tid] = a;
            if (iter == MAX_ITER - 1) g_a[batch * NN + rb + tid] = a;
        }
        __syncthreads();
#pragma unroll
        for (int r = 0; r < 8; r++) {
            float a = ash[r];
            float2 f01 = __half22float2(*(__half2*)&kv[r].x);
            float2 f23 = __half22float2(*(__half2*)&kv[r].y);
            acc.x += f01.x * a;
            acc.y += f01.y * a;
            acc.z += f23.x * a;
            acc.w += f23.y * a;
        }
        if (h == 0) __syncthreads();  // wsum/ash reuse barrier
    }

    float* T = &g_T[iter % 3][(size_t)batch * NN] + tid * 4;
    atomicAdd(T + 0, acc.x);
    atomicAdd(T + 1, acc.y);
    atomicAdd(T + 2, acc.z);
    atomicAdd(T + 3, acc.w);
}

// ---------------------------------------------------------------------------
// Epilogue (per group): read C (fp32), K = exp(-C/eps) on the fly,
// pi = K*a_i*b_j (fp32), cost_b += sum pi*C. Final T buffer: (MAX_ITER-1)%3.
__global__ void __launch_bounds__(256) epilogue(
    const float* __restrict__ C, const float* __restrict__ nu,
    float* __restrict__ out_cost, float* __restrict__ out_pi, int group_start)
{
    __shared__ float bsh[NN];
    const int blocksPerBatch = NN / 8;
    int batch = group_start + blockIdx.x / blocksPerBatch;
    int rowBase = (blockIdx.x % blocksPerBatch) * 8;
    int tid = threadIdx.x;

    const float* __restrict__ T = &g_T[(MAX_ITER - 1) % 3][(size_t)batch * NN];
    for (int j = tid; j < NN; j += 256)
        bsh[j] = (nu[(size_t)batch * NN + j] + LOGEPS) / T[j];
    __syncthreads();

    int warp = tid >> 5, lane = tid & 31;
    int row = rowBase + warp;
    float a = g_a[batch * NN + row];
    const float4* __restrict__ Crow =
        (const float4*)(C + ((size_t)batch * NN + row) * NN);
    float4* __restrict__ Prow =
        (float4*)(out_pi + ((size_t)batch * NN + row) * NN);
    const float4* __restrict__ bsh4 = (const float4*)bsh;

    float cacc = 0.0f;
#pragma unroll
    for (int k = 0; k < 8; k++) {
        int idx = k * 32 + lane;
        float4 cv = Crow[idx];
        float4 bv = bsh4[idx];
        float4 p;
        p.x = __expf(-cv.x * INV_EPS) * a * bv.x;
        p.y = __expf(-cv.y * INV_EPS) * a * bv.y;
        p.z = __expf(-cv.z * INV_EPS) * a * bv.z;
        p.w = __expf(-cv.w * INV_EPS) * a * bv.w;
        cacc += p.x * cv.x + p.y * cv.y + p.z * cv.z + p.w * cv.w;
        Prow[idx] = p;
    }
#pragma unroll
    for (int o = 16; o; o >>= 1) cacc += __shfl_xor_sync(0xffffffffu, cacc, o);
    if (lane == 0) atomicAdd(&out_cost[batch], cacc);
}

// ---------------------------------------------------------------------------
extern "C" void kernel_launch(void* const* d_in, const int* in_sizes, int n_in,
                              void* d_out, int out_size) {
    const float* mu = (const float*)d_in[0];
    const float* nu = (const float*)d_in[1];
    const float* C  = (const float*)d_in[2];
    float* cost = (float*)d_out;                 // outputs: (cost[64], pi[64M])
    float* pi   = (float*)d_out + BATCH;

    k_init<<<64, 256>>>(cost);

    const int precompBlocks = GSZ * NN * NN / (256 * 4);  // 32768
    for (int g = 0; g < BATCH / GSZ; g++) {
        int start = g * GSZ;
        k_precompute16<<<precompBlocks, 256>>>(C, start);
        for (int it = 0; it < MAX_ITER; it++) {
            fused_iter<<<GSZ * BPB, 256>>>(mu, nu, start, it);
        }
        epilogue<<<GSZ * (NN / 8), 256>>>(C, nu, cost, pi, start);
    }
}